// round 2
// baseline (speedup 1.0000x reference)
#include <cuda_runtime.h>

#define NN 50000
#define EE 800000
#define TT 3
#define HH 8
#define D1 64
#define C2 16

// ---------------- scratch (static device globals; no allocation) ----------------
__device__ float g_feat1[NN * TT * D1];   // 38.4 MB  per-(node,type) layer0 features
__device__ float g_es1[NN * TT * HH];     // 4.8 MB   exp(leakyrelu(score)) layer0
__device__ float g_h[NN * D1];            // 12.8 MB  layer0 output
__device__ float g_feat2[NN * TT * C2];   // 9.6 MB
__device__ float g_es2[NN * TT];          // 0.6 MB
__device__ float g_resid[NN * C2];        // 3.2 MB   h@res_w + b
__device__ float g_u1[TT * D1 * HH];      // attention row-sum vectors, layer0
__device__ float g_u2[TT * C2];           // layer1
__device__ float g_Wc[D1 * 64];           // combined [W2(t=0..2) | res_w] weights
__device__ int   g_deg[NN];
__device__ int   g_rowptr[NN + 1];
__device__ int   g_cursor[NN];
__device__ int   g_gather[EE];            // CSR payload: src*3 + etype

// ---------------- setup: zero deg/out, build u1/u2/Wc ----------------
__global__ void k_setup(const float* __restrict__ al1, const float* __restrict__ ar1,
                        const float* __restrict__ al2, const float* __restrict__ ar2,
                        const float* __restrict__ W2, const float* __restrict__ res_w,
                        float* __restrict__ d_out) {
    int b = blockIdx.x;
    int tid = threadIdx.x;
    const int ZB = (NN + 255) / 256;  // 196 blocks to zero deg
    if (b < ZB) {
        int i = b * 256 + tid;
        if (i < NN) g_deg[i] = 0;
        if (b == 0 && tid < C2) d_out[tid] = 0.f;
        return;
    }
    b -= ZB;
    if (b < 6) {  // u1: 1536 entries, u1[(t*64+i)*8+h] = sum_d (al1+ar1)[t,i,h*8+d]
        int i = b * 256 + tid;
        if (i < TT * D1 * HH) {
            int h = i & 7;
            int ti = i >> 3;  // t*64 + row
            const float* pl = al1 + ti * 64 + h * 8;
            const float* pr = ar1 + ti * 64 + h * 8;
            float s = 0.f;
#pragma unroll
            for (int d = 0; d < 8; d++) s += pl[d] + pr[d];
            g_u1[i] = s;
        }
        return;
    }
    b -= 6;
    if (b < 1) {  // u2: 48 entries, u2[t*16+i] = sum_j (al2+ar2)[t,i,j]
        int i = tid;
        if (i < TT * C2) {
            const float* pl = al2 + i * 16;
            const float* pr = ar2 + i * 16;
            float s = 0.f;
#pragma unroll
            for (int j = 0; j < 16; j++) s += pl[j] + pr[j];
            g_u2[i] = s;
        }
        return;
    }
    b -= 1;
    if (b < 16) {  // Wc: 4096 entries. cols 0..47 = W2[t], cols 48..63 = res_w
        int i = b * 256 + tid;  // i = k*64 + c
        int k = i >> 6, c = i & 63;
        float v;
        if (c < 48) v = W2[(((c >> 4) * D1) + k) * C2 + (c & 15)];
        else        v = res_w[k * C2 + (c - 48)];
        g_Wc[i] = v;
        return;
    }
}

// ---------------- CSR build ----------------
__global__ void k_hist(const int* __restrict__ dst) {
    int e = blockIdx.x * 256 + threadIdx.x;
    if (e < EE) atomicAdd(&g_deg[dst[e]], 1);
}

__global__ void k_scan() {  // single block, 1024 threads
    __shared__ int ss[1024];
    const int CH = 49;  // 1024*49 >= 50001
    int tid = threadIdx.x;
    int base = tid * CH;
    int s = 0;
    for (int i = 0; i < CH; i++) {
        int j = base + i;
        if (j < NN) s += g_deg[j];
    }
    ss[tid] = s;
    __syncthreads();
    for (int off = 1; off < 1024; off <<= 1) {
        int v = (tid >= off) ? ss[tid - off] : 0;
        __syncthreads();
        ss[tid] += v;
        __syncthreads();
    }
    int run = (tid > 0) ? ss[tid - 1] : 0;
    for (int i = 0; i < CH; i++) {
        int j = base + i;
        if (j <= NN) {
            g_rowptr[j] = run;
            if (j < NN) {
                g_cursor[j] = run;
                run += g_deg[j];
            }
        }
    }
}

__global__ void k_scatter(const int* __restrict__ src, const int* __restrict__ dst,
                          const int* __restrict__ etype) {
    int e = blockIdx.x * 256 + threadIdx.x;
    if (e < EE) {
        int d = dst[e];
        int pos = atomicAdd(&g_cursor[d], 1);
        g_gather[pos] = src[e] * TT + etype[e];
    }
}

// ---------------- layer 0 GEMM: feat1[n,t,:] = x[n,:] @ W1[t] ----------------
__global__ void __launch_bounds__(256) k_feat1(const float* __restrict__ x,
                                               const float* __restrict__ W1) {
    __shared__ float xs[64][68];
    __shared__ float ws[64][68];
    int t = blockIdx.y;
    int r0 = blockIdx.x * 64;
    int tid = threadIdx.x;
    for (int i = tid; i < 64 * 16; i += 256) {
        int r = i >> 4, c4 = (i & 15) << 2;
        float4 v = make_float4(0.f, 0.f, 0.f, 0.f);
        if (r0 + r < NN) v = *reinterpret_cast<const float4*>(x + (r0 + r) * 64 + c4);
        *reinterpret_cast<float4*>(&xs[r][c4]) = v;
        float4 w = *reinterpret_cast<const float4*>(W1 + (t * 64 + r) * 64 + c4);
        *reinterpret_cast<float4*>(&ws[r][c4]) = w;
    }
    __syncthreads();
    int cc = (tid & 15) << 2;
    int rr = (tid >> 4) << 2;
    float acc[4][4] = {};
#pragma unroll
    for (int k = 0; k < 64; k++) {
        float a0 = xs[rr][k], a1 = xs[rr + 1][k], a2 = xs[rr + 2][k], a3 = xs[rr + 3][k];
        float4 bv = *reinterpret_cast<const float4*>(&ws[k][cc]);
        acc[0][0] = fmaf(a0, bv.x, acc[0][0]); acc[0][1] = fmaf(a0, bv.y, acc[0][1]);
        acc[0][2] = fmaf(a0, bv.z, acc[0][2]); acc[0][3] = fmaf(a0, bv.w, acc[0][3]);
        acc[1][0] = fmaf(a1, bv.x, acc[1][0]); acc[1][1] = fmaf(a1, bv.y, acc[1][1]);
        acc[1][2] = fmaf(a1, bv.z, acc[1][2]); acc[1][3] = fmaf(a1, bv.w, acc[1][3]);
        acc[2][0] = fmaf(a2, bv.x, acc[2][0]); acc[2][1] = fmaf(a2, bv.y, acc[2][1]);
        acc[2][2] = fmaf(a2, bv.z, acc[2][2]); acc[2][3] = fmaf(a2, bv.w, acc[2][3]);
        acc[3][0] = fmaf(a3, bv.x, acc[3][0]); acc[3][1] = fmaf(a3, bv.y, acc[3][1]);
        acc[3][2] = fmaf(a3, bv.z, acc[3][2]); acc[3][3] = fmaf(a3, bv.w, acc[3][3]);
    }
#pragma unroll
    for (int i2 = 0; i2 < 4; i2++) {
        int r = r0 + rr + i2;
        if (r < NN) {
            float4 o = make_float4(acc[i2][0], acc[i2][1], acc[i2][2], acc[i2][3]);
            *reinterpret_cast<float4*>(&g_feat1[(r * TT + t) * 64 + cc]) = o;
        }
    }
}

// ---------------- es1[n,t,h] = exp(leakyrelu(feat1 . u1[t,:,h])) ----------------
__global__ void k_es1() {
    int idx = blockIdx.x * 256 + threadIdx.x;
    if (idx >= NN * TT) return;
    int t = idx % TT;
    const float* f = g_feat1 + idx * 64;
    const float* u = g_u1 + t * 64 * 8;
    float s[8] = {0.f, 0.f, 0.f, 0.f, 0.f, 0.f, 0.f, 0.f};
#pragma unroll 8
    for (int i = 0; i < 64; i++) {
        float fv = __ldg(&f[i]);
#pragma unroll
        for (int h = 0; h < 8; h++) s[h] = fmaf(fv, __ldg(&u[i * 8 + h]), s[h]);
    }
#pragma unroll
    for (int h = 0; h < 8; h++) {
        float a = s[h];
        a = a > 0.f ? a : 0.2f * a;
        g_es1[idx * 8 + h] = expf(a);
    }
}

// ---------------- layer0 aggregation: softmax-weighted segment sum, fused ELU ----------------
__global__ void __launch_bounds__(256) k_agg1() {
    int node = blockIdx.x * 4 + (threadIdx.x >> 6);
    int j = threadIdx.x & 63;
    int h = j >> 3;
    if (node >= NN) return;
    int beg = g_rowptr[node], end = g_rowptr[node + 1];
    float acc = 0.f, wsum = 0.f;
#pragma unroll 4
    for (int p = beg; p < end; p++) {
        int g = __ldg(&g_gather[p]);
        float w = __ldg(&g_es1[g * 8 + h]);
        acc = fmaf(__ldg(&g_feat1[g * 64 + j]), w, acc);
        wsum += w;
    }
    float v = (end > beg) ? acc / wsum : 0.f;
    v = v > 0.f ? v : (expf(v) - 1.f);  // ELU
    g_h[node * 64 + j] = v;
}

// ---------------- layer 1 GEMM: [feat2 | resid] = h @ Wc (+bias on resid cols) ----------------
__global__ void __launch_bounds__(256) k_feat2(const float* __restrict__ res_b) {
    __shared__ float xs[64][68];
    __shared__ float ws[64][68];
    int r0 = blockIdx.x * 64;
    int tid = threadIdx.x;
    for (int i = tid; i < 64 * 16; i += 256) {
        int r = i >> 4, c4 = (i & 15) << 2;
        float4 v = make_float4(0.f, 0.f, 0.f, 0.f);
        if (r0 + r < NN) v = *reinterpret_cast<const float4*>(g_h + (r0 + r) * 64 + c4);
        *reinterpret_cast<float4*>(&xs[r][c4]) = v;
        float4 w = *reinterpret_cast<const float4*>(g_Wc + r * 64 + c4);
        *reinterpret_cast<float4*>(&ws[r][c4]) = w;
    }
    __syncthreads();
    int cc = (tid & 15) << 2;
    int rr = (tid >> 4) << 2;
    float acc[4][4] = {};
#pragma unroll
    for (int k = 0; k < 64; k++) {
        float a0 = xs[rr][k], a1 = xs[rr + 1][k], a2 = xs[rr + 2][k], a3 = xs[rr + 3][k];
        float4 bv = *reinterpret_cast<const float4*>(&ws[k][cc]);
        acc[0][0] = fmaf(a0, bv.x, acc[0][0]); acc[0][1] = fmaf(a0, bv.y, acc[0][1]);
        acc[0][2] = fmaf(a0, bv.z, acc[0][2]); acc[0][3] = fmaf(a0, bv.w, acc[0][3]);
        acc[1][0] = fmaf(a1, bv.x, acc[1][0]); acc[1][1] = fmaf(a1, bv.y, acc[1][1]);
        acc[1][2] = fmaf(a1, bv.z, acc[1][2]); acc[1][3] = fmaf(a1, bv.w, acc[1][3]);
        acc[2][0] = fmaf(a2, bv.x, acc[2][0]); acc[2][1] = fmaf(a2, bv.y, acc[2][1]);
        acc[2][2] = fmaf(a2, bv.z, acc[2][2]); acc[2][3] = fmaf(a2, bv.w, acc[2][3]);
        acc[3][0] = fmaf(a3, bv.x, acc[3][0]); acc[3][1] = fmaf(a3, bv.y, acc[3][1]);
        acc[3][2] = fmaf(a3, bv.z, acc[3][2]); acc[3][3] = fmaf(a3, bv.w, acc[3][3]);
    }
#pragma unroll
    for (int i2 = 0; i2 < 4; i2++) {
        int r = r0 + rr + i2;
        if (r < NN) {
            if (cc < 48) {
                int t = cc >> 4;
                float4 o = make_float4(acc[i2][0], acc[i2][1], acc[i2][2], acc[i2][3]);
                *reinterpret_cast<float4*>(&g_feat2[(r * TT + t) * 16 + (cc & 15)]) = o;
            } else {
                int c0 = cc - 48;
                float4 o = make_float4(acc[i2][0] + res_b[c0], acc[i2][1] + res_b[c0 + 1],
                                       acc[i2][2] + res_b[c0 + 2], acc[i2][3] + res_b[c0 + 3]);
                *reinterpret_cast<float4*>(&g_resid[r * 16 + c0]) = o;
            }
        }
    }
}

// ---------------- es2[n,t] = exp(leakyrelu(feat2 . u2[t])) ----------------
__global__ void k_es2() {
    int idx = blockIdx.x * 256 + threadIdx.x;
    if (idx >= NN * TT) return;
    int t = idx % TT;
    const float* f = g_feat2 + idx * 16;
    const float* u = g_u2 + t * 16;
    float s = 0.f;
#pragma unroll
    for (int i = 0; i < 16; i++) s = fmaf(__ldg(&f[i]), __ldg(&u[i]), s);
    s = s > 0.f ? s : 0.2f * s;
    g_es2[idx] = expf(s);
}

// ---------------- layer1 aggregation + residual + mean pooling ----------------
__global__ void __launch_bounds__(256) k_agg2(float* __restrict__ d_out) {
    __shared__ float red[256];
    int node = blockIdx.x * 16 + (threadIdx.x >> 4);
    int j = threadIdx.x & 15;
    float val = 0.f;
    if (node < NN) {
        int beg = g_rowptr[node], end = g_rowptr[node + 1];
        float acc = 0.f, wsum = 0.f;
#pragma unroll 4
        for (int p = beg; p < end; p++) {
            int g = __ldg(&g_gather[p]);
            float w = __ldg(&g_es2[g]);
            acc = fmaf(__ldg(&g_feat2[g * 16 + j]), w, acc);
            wsum += w;
        }
        val = ((end > beg) ? acc / wsum : 0.f) + g_resid[node * 16 + j];
    }
    red[threadIdx.x] = val * (1.0f / NN);
    __syncthreads();
#pragma unroll
    for (int s = 8; s > 0; s >>= 1) {
        if ((threadIdx.x >> 4) < s) red[threadIdx.x] += red[threadIdx.x + s * 16];
        __syncthreads();
    }
    if (threadIdx.x < 16) atomicAdd(&d_out[threadIdx.x], red[threadIdx.x]);
}

// ---------------- launch ----------------
extern "C" void kernel_launch(void* const* d_in, const int* in_sizes, int n_in,
                              void* d_out, int out_size) {
    const float* x     = (const float*)d_in[0];
    const int*   src   = (const int*)d_in[1];
    const int*   dst   = (const int*)d_in[2];
    // d_in[3] = ntype (unused by reference math)
    const int*   etype = (const int*)d_in[4];
    const float* W1    = (const float*)d_in[5];
    const float* al1   = (const float*)d_in[6];
    const float* ar1   = (const float*)d_in[7];
    const float* W2    = (const float*)d_in[8];
    const float* al2   = (const float*)d_in[9];
    const float* ar2   = (const float*)d_in[10];
    const float* res_w = (const float*)d_in[11];
    const float* res_b = (const float*)d_in[12];
    float* out = (float*)d_out;

    const int ZB = (NN + 255) / 256;
    k_setup<<<ZB + 6 + 1 + 16, 256>>>(al1, ar1, al2, ar2, W2, res_w, out);
    k_hist<<<(EE + 255) / 256, 256>>>(dst);
    k_scan<<<1, 1024>>>();
    k_scatter<<<(EE + 255) / 256, 256>>>(src, dst, etype);
    k_feat1<<<dim3((NN + 63) / 64, TT), 256>>>(x, W1);
    k_es1<<<(NN * TT + 255) / 256, 256>>>();
    k_agg1<<<(NN + 3) / 4, 256>>>();
    k_feat2<<<(NN + 63) / 64, 256>>>(res_b);
    k_es2<<<(NN * TT + 255) / 256, 256>>>();
    k_agg2<<<(NN + 15) / 16, 256>>>(out);
}

// round 4
// speedup vs baseline: 1.6626x; 1.6626x over previous
#include <cuda_runtime.h>

#define NN 50000
#define EE 800000
#define TT 3
#define HH 8
#define D1 64
#define C2 16

// ---------------- scratch (static device globals; no allocation) ----------------
__device__ float g_feat1[NN * TT * D1];   // 38.4 MB per-(node,type) layer0 features
__device__ float g_es1[NN * TT * HH];     // 4.8 MB  exp(leakyrelu(score)) layer0, [n][t][h]
__device__ float g_h[NN * D1];            // 12.8 MB layer0 output
__device__ float g_feat2[NN * TT * C2];   // 9.6 MB
__device__ float g_es2[NN * TT];          // 0.6 MB  [n][t]
__device__ float g_resid[NN * C2];        // 3.2 MB  h@res_w + b
__device__ float g_v1[D1 * TT * HH];      // [i][t*8+h] : W1[t]^T-contracted attention vec
__device__ float g_v2[TT * D1];           // [t][i]
__device__ float g_Wc[D1 * 64];           // combined [W2(t=0..2) | res_w]
__device__ int   g_deg[NN];               // zero at load; re-zeroed by k_scatter tail
__device__ int   g_rowptr[NN + 1];
__device__ int   g_cursor[NN];
__device__ int   g_gather[EE];            // CSR payload: src*3 + etype

#define HIST_BLOCKS ((EE + 1023) / 1024)  // 782, 4 edges/thread

// ---------------- setup: hist + zero d_out + build v1/v2/Wc ----------------
__global__ void k_setup(const float* __restrict__ al1, const float* __restrict__ ar1,
                        const float* __restrict__ al2, const float* __restrict__ ar2,
                        const float* __restrict__ W1, const float* __restrict__ W2,
                        const float* __restrict__ res_w, const int* __restrict__ dst,
                        float* __restrict__ d_out) {
    int b = blockIdx.x;
    int tid = threadIdx.x;
    if (b < HIST_BLOCKS) {  // histogram of dst, 4 independent REDG per thread
        int t0 = b * 1024 + tid;
#pragma unroll
        for (int k = 0; k < 4; k++) {
            int e = t0 + k * 256;
            if (e < EE) atomicAdd(&g_deg[dst[e]], 1);
        }
        return;
    }
    b -= HIST_BLOCKS;
    if (b < TT) {  // v1 for type t=b:  v1[i][h] = sum_c W1[t][i][c] * u1[t][c][h]
        int t = b;
        __shared__ float u1s[64][8];
        for (int e = tid; e < 512; e += 256) {
            int c = e >> 3, h = e & 7;
            const float* pl = al1 + t * 4096 + c * 64 + h * 8;
            const float* pr = ar1 + t * 4096 + c * 64 + h * 8;
            float s = 0.f;
#pragma unroll
            for (int d = 0; d < 8; d++) s += pl[d] + pr[d];
            u1s[c][h] = s;
        }
        __syncthreads();
        for (int e = tid; e < 512; e += 256) {
            int i = e >> 3, h = e & 7;
            const float* w = W1 + t * 4096 + i * 64;
            float s = 0.f;
#pragma unroll 8
            for (int c = 0; c < 64; c++) s = fmaf(w[c], u1s[c][h], s);
            g_v1[i * 24 + t * 8 + h] = s;
        }
        return;
    }
    b -= TT;
    if (b < 1) {  // v2[t][i] = sum_c W2[t][i][c] * u2[t][c]; also zero d_out
        __shared__ float u2s[48];
        if (tid < 48) {
            int t = tid >> 4, c = tid & 15;
            const float* pl = al2 + (t * 16 + c) * 16;
            const float* pr = ar2 + (t * 16 + c) * 16;
            float s = 0.f;
#pragma unroll
            for (int j = 0; j < 16; j++) s += pl[j] + pr[j];
            u2s[tid] = s;
        }
        if (tid >= 240 && tid < 240 + C2) d_out[tid - 240] = 0.f;
        __syncthreads();
        if (tid < 192) {
            int t = tid >> 6, i = tid & 63;
            const float* w = W2 + (t * 64 + i) * 16;
            float s = 0.f;
#pragma unroll
            for (int c = 0; c < 16; c++) s = fmaf(w[c], u2s[t * 16 + c], s);
            g_v2[tid] = s;
        }
        return;
    }
    b -= 1;
    if (b < 16) {  // Wc: cols 0..47 = W2[t], cols 48..63 = res_w
        int i = b * 256 + tid;  // i = k*64 + c
        int k = i >> 6, c = i & 63;
        float v;
        if (c < 48) v = W2[(((c >> 4) * D1) + k) * C2 + (c & 15)];
        else        v = res_w[k * C2 + (c - 48)];
        g_Wc[i] = v;
        return;
    }
}

// ---------------- scan: smem-staged coalesced exclusive prefix ----------------
__global__ void k_scan() {  // single block, 1024 threads, NN*4 dynamic smem
    extern __shared__ int sdeg[];
    __shared__ int ss[1024];
    int tid = threadIdx.x;
    for (int i = tid; i < NN; i += 1024) sdeg[i] = g_deg[i];   // coalesced in
    __syncthreads();
    const int CH = 49;  // 1024*49 >= 50000
    int base = tid * CH;
    int s = 0;
    for (int i = 0; i < CH; i++) {
        int j = base + i;
        if (j < NN) s += sdeg[j];
    }
    ss[tid] = s;
    __syncthreads();
    for (int off = 1; off < 1024; off <<= 1) {
        int v = (tid >= off) ? ss[tid - off] : 0;
        __syncthreads();
        ss[tid] += v;
        __syncthreads();
    }
    if (tid == 1023) g_rowptr[NN] = ss[1023];
    int run = (tid > 0) ? ss[tid - 1] : 0;
    for (int i = 0; i < CH; i++) {  // in-place exclusive scan in smem
        int j = base + i;
        if (j < NN) {
            int d = sdeg[j];
            sdeg[j] = run;
            run += d;
        }
    }
    __syncthreads();
    for (int i = tid; i < NN; i += 1024) {  // coalesced out
        int v = sdeg[i];
        g_rowptr[i] = v;
        g_cursor[i] = v;
    }
}

// ---------------- scatter (ILP 4) + re-zero deg for next call ----------------
__global__ void k_scatter(const int* __restrict__ src, const int* __restrict__ dst,
                          const int* __restrict__ etype) {
    int t0 = blockIdx.x * 1024 + threadIdx.x;
#pragma unroll
    for (int k = 0; k < 4; k++) {
        int e = t0 + k * 256;
        if (e < EE) {
            int pos = atomicAdd(&g_cursor[dst[e]], 1);
            g_gather[pos] = src[e] * TT + etype[e];
        }
    }
    int gt = blockIdx.x * 256 + threadIdx.x;  // deg consumed by k_scan; reset now
    for (int i = gt; i < NN; i += gridDim.x * 256) g_deg[i] = 0;
}

// ---------------- layer0 compute: y<3 -> feat1[n,t,:]=x@W1[t]; y==3 -> es1 ----------------
__global__ void __launch_bounds__(256) k_l1(const float* __restrict__ x,
                                            const float* __restrict__ W1) {
    __shared__ float xs[64][68];
    __shared__ float ws[64][68];
    int r0 = blockIdx.x * 64;
    int tid = threadIdx.x;
    // load x tile (common)
    for (int i = tid; i < 64 * 16; i += 256) {
        int r = i >> 4, c4 = (i & 15) << 2;
        float4 v = make_float4(0.f, 0.f, 0.f, 0.f);
        if (r0 + r < NN) v = *reinterpret_cast<const float4*>(x + (r0 + r) * 64 + c4);
        *reinterpret_cast<float4*>(&xs[r][c4]) = v;
    }
    if (blockIdx.y < 3) {
        int t = blockIdx.y;
        for (int i = tid; i < 64 * 16; i += 256) {
            int r = i >> 4, c4 = (i & 15) << 2;
            float4 w = *reinterpret_cast<const float4*>(W1 + (t * 64 + r) * 64 + c4);
            *reinterpret_cast<float4*>(&ws[r][c4]) = w;
        }
        __syncthreads();
        int cc = (tid & 15) << 2;
        int rr = (tid >> 4) << 2;
        float acc[4][4] = {};
#pragma unroll
        for (int k = 0; k < 64; k++) {
            float a0 = xs[rr][k], a1 = xs[rr + 1][k], a2 = xs[rr + 2][k], a3 = xs[rr + 3][k];
            float4 bv = *reinterpret_cast<const float4*>(&ws[k][cc]);
            acc[0][0] = fmaf(a0, bv.x, acc[0][0]); acc[0][1] = fmaf(a0, bv.y, acc[0][1]);
            acc[0][2] = fmaf(a0, bv.z, acc[0][2]); acc[0][3] = fmaf(a0, bv.w, acc[0][3]);
            acc[1][0] = fmaf(a1, bv.x, acc[1][0]); acc[1][1] = fmaf(a1, bv.y, acc[1][1]);
            acc[1][2] = fmaf(a1, bv.z, acc[1][2]); acc[1][3] = fmaf(a1, bv.w, acc[1][3]);
            acc[2][0] = fmaf(a2, bv.x, acc[2][0]); acc[2][1] = fmaf(a2, bv.y, acc[2][1]);
            acc[2][2] = fmaf(a2, bv.z, acc[2][2]); acc[2][3] = fmaf(a2, bv.w, acc[2][3]);
            acc[3][0] = fmaf(a3, bv.x, acc[3][0]); acc[3][1] = fmaf(a3, bv.y, acc[3][1]);
            acc[3][2] = fmaf(a3, bv.z, acc[3][2]); acc[3][3] = fmaf(a3, bv.w, acc[3][3]);
        }
#pragma unroll
        for (int i2 = 0; i2 < 4; i2++) {
            int r = r0 + rr + i2;
            if (r < NN) {
                float4 o = make_float4(acc[i2][0], acc[i2][1], acc[i2][2], acc[i2][3]);
                *reinterpret_cast<float4*>(&g_feat1[(r * TT + t) * 64 + cc]) = o;
            }
        }
    } else {
        // es1[n][t*8+h] = exp(leakyrelu( x[n,:] . v1[:, t*8+h] ))
        for (int i2 = tid; i2 < 64 * 24; i2 += 256) {
            int r = i2 / 24, c = i2 - r * 24;
            ws[r][c] = g_v1[i2];
        }
        __syncthreads();
        int row = tid >> 2;
        int c0 = (tid & 3) * 6;
        float s[6] = {0.f, 0.f, 0.f, 0.f, 0.f, 0.f};
#pragma unroll 8
        for (int i = 0; i < 64; i++) {
            float xv = xs[row][i];
#pragma unroll
            for (int c = 0; c < 6; c++) s[c] = fmaf(xv, ws[i][c0 + c], s[c]);
        }
        int n = r0 + row;
        if (n < NN) {
#pragma unroll
            for (int c = 0; c < 6; c++) {
                float a = s[c];
                a = a > 0.f ? a : 0.2f * a;
                g_es1[n * 24 + c0 + c] = expf(a);
            }
        }
    }
}

// ---------------- layer0 aggregation + fused layer1 score (es2) ----------------
__global__ void __launch_bounds__(256) k_agg1() {
    __shared__ float v2s[3][64];
    __shared__ float part[4][2][3];
    int tid = threadIdx.x;
    if (tid < 192) v2s[tid >> 6][tid & 63] = g_v2[tid];
    int node = blockIdx.x * 4 + (tid >> 6);
    int j = tid & 63;
    int h = j >> 3;
    float v = 0.f;
    if (node < NN) {
        int beg = g_rowptr[node], end = g_rowptr[node + 1];
        float acc = 0.f, wsum = 0.f;
#pragma unroll 4
        for (int p = beg; p < end; p++) {
            int g = __ldg(&g_gather[p]);
            float w = __ldg(&g_es1[g * 8 + h]);
            acc = fmaf(__ldg(&g_feat1[g * 64 + j]), w, acc);
            wsum += w;
        }
        v = (end > beg) ? acc / wsum : 0.f;
        v = v > 0.f ? v : (expf(v) - 1.f);  // ELU
        g_h[node * 64 + j] = v;
    }
    __syncthreads();  // v2s ready
    float p0 = v * v2s[0][j];
    float p1 = v * v2s[1][j];
    float p2 = v * v2s[2][j];
#pragma unroll
    for (int off = 16; off > 0; off >>= 1) {
        p0 += __shfl_down_sync(0xffffffffu, p0, off);
        p1 += __shfl_down_sync(0xffffffffu, p1, off);
        p2 += __shfl_down_sync(0xffffffffu, p2, off);
    }
    if ((tid & 31) == 0) {
        int nib = tid >> 6, wh = (tid >> 5) & 1;
        part[nib][wh][0] = p0;
        part[nib][wh][1] = p1;
        part[nib][wh][2] = p2;
    }
    __syncthreads();
    if (tid < 16) {  // FIXED: was tid<12, which skipped node 3 of each block -> es2=0 -> 0/0 NaN
        int nib = tid >> 2, t = tid & 3;
        if (t < 3) {
            int nd = blockIdx.x * 4 + nib;
            if (nd < NN) {
                float s = part[nib][0][t] + part[nib][1][t];
                s = s > 0.f ? s : 0.2f * s;
                g_es2[nd * 3 + t] = expf(s);
            }
        }
    }
}

// ---------------- layer 1 GEMM: [feat2 | resid] = h @ Wc (+bias on resid cols) ----------------
__global__ void __launch_bounds__(256) k_feat2(const float* __restrict__ res_b) {
    __shared__ float xs[64][68];
    __shared__ float ws[64][68];
    int r0 = blockIdx.x * 64;
    int tid = threadIdx.x;
    for (int i = tid; i < 64 * 16; i += 256) {
        int r = i >> 4, c4 = (i & 15) << 2;
        float4 v = make_float4(0.f, 0.f, 0.f, 0.f);
        if (r0 + r < NN) v = *reinterpret_cast<const float4*>(g_h + (r0 + r) * 64 + c4);
        *reinterpret_cast<float4*>(&xs[r][c4]) = v;
        float4 w = *reinterpret_cast<const float4*>(g_Wc + r * 64 + c4);
        *reinterpret_cast<float4*>(&ws[r][c4]) = w;
    }
    __syncthreads();
    int cc = (tid & 15) << 2;
    int rr = (tid >> 4) << 2;
    float acc[4][4] = {};
#pragma unroll
    for (int k = 0; k < 64; k++) {
        float a0 = xs[rr][k], a1 = xs[rr + 1][k], a2 = xs[rr + 2][k], a3 = xs[rr + 3][k];
        float4 bv = *reinterpret_cast<const float4*>(&ws[k][cc]);
        acc[0][0] = fmaf(a0, bv.x, acc[0][0]); acc[0][1] = fmaf(a0, bv.y, acc[0][1]);
        acc[0][2] = fmaf(a0, bv.z, acc[0][2]); acc[0][3] = fmaf(a0, bv.w, acc[0][3]);
        acc[1][0] = fmaf(a1, bv.x, acc[1][0]); acc[1][1] = fmaf(a1, bv.y, acc[1][1]);
        acc[1][2] = fmaf(a1, bv.z, acc[1][2]); acc[1][3] = fmaf(a1, bv.w, acc[1][3]);
        acc[2][0] = fmaf(a2, bv.x, acc[2][0]); acc[2][1] = fmaf(a2, bv.y, acc[2][1]);
        acc[2][2] = fmaf(a2, bv.z, acc[2][2]); acc[2][3] = fmaf(a2, bv.w, acc[2][3]);
        acc[3][0] = fmaf(a3, bv.x, acc[3][0]); acc[3][1] = fmaf(a3, bv.y, acc[3][1]);
        acc[3][2] = fmaf(a3, bv.z, acc[3][2]); acc[3][3] = fmaf(a3, bv.w, acc[3][3]);
    }
#pragma unroll
    for (int i2 = 0; i2 < 4; i2++) {
        int r = r0 + rr + i2;
        if (r < NN) {
            if (cc < 48) {
                int t = cc >> 4;
                float4 o = make_float4(acc[i2][0], acc[i2][1], acc[i2][2], acc[i2][3]);
                *reinterpret_cast<float4*>(&g_feat2[(r * TT + t) * 16 + (cc & 15)]) = o;
            } else {
                int c0 = cc - 48;
                float4 o = make_float4(acc[i2][0] + res_b[c0], acc[i2][1] + res_b[c0 + 1],
                                       acc[i2][2] + res_b[c0 + 2], acc[i2][3] + res_b[c0 + 3]);
                *reinterpret_cast<float4*>(&g_resid[r * 16 + c0]) = o;
            }
        }
    }
}

// ---------------- layer1 aggregation + residual + mean pooling ----------------
__global__ void __launch_bounds__(256) k_agg2(float* __restrict__ d_out) {
    __shared__ float red[256];
    int node = blockIdx.x * 16 + (threadIdx.x >> 4);
    int j = threadIdx.x & 15;
    float val = 0.f;
    if (node < NN) {
        int beg = g_rowptr[node], end = g_rowptr[node + 1];
        float acc = 0.f, wsum = 0.f;
#pragma unroll 4
        for (int p = beg; p < end; p++) {
            int g = __ldg(&g_gather[p]);
            float w = __ldg(&g_es2[g]);
            acc = fmaf(__ldg(&g_feat2[g * 16 + j]), w, acc);
            wsum += w;
        }
        val = ((end > beg) ? acc / wsum : 0.f) + g_resid[node * 16 + j];
    }
    red[threadIdx.x] = val * (1.0f / NN);
    __syncthreads();
#pragma unroll
    for (int s = 8; s > 0; s >>= 1) {
        if ((threadIdx.x >> 4) < s) red[threadIdx.x] += red[threadIdx.x + s * 16];
        __syncthreads();
    }
    if (threadIdx.x < 16) atomicAdd(&d_out[threadIdx.x], red[threadIdx.x]);
}

// ---------------- launch ----------------
extern "C" void kernel_launch(void* const* d_in, const int* in_sizes, int n_in,
                              void* d_out, int out_size) {
    const float* x     = (const float*)d_in[0];
    const int*   src   = (const int*)d_in[1];
    const int*   dst   = (const int*)d_in[2];
    // d_in[3] = ntype (unused by reference math)
    const int*   etype = (const int*)d_in[4];
    const float* W1    = (const float*)d_in[5];
    const float* al1   = (const float*)d_in[6];
    const float* ar1   = (const float*)d_in[7];
    const float* W2    = (const float*)d_in[8];
    const float* al2   = (const float*)d_in[9];
    const float* ar2   = (const float*)d_in[10];
    const float* res_w = (const float*)d_in[11];
    const float* res_b = (const float*)d_in[12];
    float* out = (float*)d_out;

    cudaFuncSetAttribute(k_scan, cudaFuncAttributeMaxDynamicSharedMemorySize, NN * 4);

    k_setup<<<HIST_BLOCKS + TT + 1 + 16, 256>>>(al1, ar1, al2, ar2, W1, W2, res_w, dst, out);
    k_scan<<<1, 1024, NN * 4>>>();
    k_scatter<<<HIST_BLOCKS, 256>>>(src, dst, etype);
    k_l1<<<dim3((NN + 63) / 64, 4), 256>>>(x, W1);
    k_agg1<<<(NN + 3) / 4, 256>>>();
    k_feat2<<<(NN + 63) / 64, 256>>>(res_b);
    k_agg2<<<(NN + 15) / 16, 256>>>(out);
}